// round 13
// baseline (speedup 1.0000x reference)
#include <cuda_runtime.h>
#include <cuda_fp16.h>
#include <math.h>
#include <stdint.h>

#define BB 64
#define SS 4096
#define HH 256
#define NTILES 4096            // BB*SS/64  (M=64 tiles)

// ---------------- device-global scratch (no allocation allowed) -------------
__device__ float g_u[BB * HH];            // W_t @ o_last per batch (fp32)
__device__ uint4 g_Bh[16 * 16 * 32];      // W_F fp16 m16n8k16 B-fragment image (128 KB)
__device__ float g_pT[NTILES * HH];
__device__ float g_pF[NTILES * HH];
__device__ float g_mT[NTILES], g_sT[NTILES], g_mF[NTILES], g_sF[NTILES];

// ---------------- SMEM map (bytes), 93824 total -> 2 CTAs/SM ----------------
#define AH_OFF    0            // 4 slots x 4096 (64 rows x 64B fp16) = 16384
#define B_OFF     16384        // 4 slots x 16384 = 65536 (fp16 fragments)
#define USH_OFF   81920        // 256 floats
#define VSH_OFF   82944        // 256 floats
#define SCT_OFF   83968        // 64 floats
#define SCF_OFF   84224        // 64 floats
#define SCFR_OFF  84480        // 4 x 64 floats = 1024
#define RED_OFF   85504        // 32 floats
#define PTS_OFF   85632        // 4 x 256 floats = 4096
#define PFS_OFF   89728        // 4 x 256 floats = 4096
#define SMEM_TOTAL 93824

// ---------------- helpers ----------------------------------------------------
__device__ __forceinline__ uint32_t packh2(float lo, float hi) {
    __half2 h = __floats2half2_rn(lo, hi);
    return *(uint32_t*)&h;
}
__device__ __forceinline__ float tanha(float x) {
    float y;
    asm("tanh.approx.f32 %0, %1;" : "=f"(y) : "f"(x));
    return y;
}
__device__ __forceinline__ void mma16(float* c, uint32_t a0, uint32_t a1,
                                      uint32_t a2, uint32_t a3,
                                      uint32_t b0, uint32_t b1) {
    asm volatile(
        "mma.sync.aligned.m16n8k16.row.col.f32.f16.f16.f32 "
        "{%0,%1,%2,%3}, {%4,%5,%6,%7}, {%8,%9}, {%0,%1,%2,%3};"
        : "+f"(c[0]), "+f"(c[1]), "+f"(c[2]), "+f"(c[3])
        : "r"(a0), "r"(a1), "r"(a2), "r"(a3), "r"(b0), "r"(b1));
}
__device__ __forceinline__ void ldsm4(uint32_t* a, uint32_t addr) {
    asm volatile("ldmatrix.sync.aligned.m8n8.x4.shared.b16 {%0,%1,%2,%3}, [%4];"
                 : "=r"(a[0]), "=r"(a[1]), "=r"(a[2]), "=r"(a[3]) : "r"(addr));
}
#define CP16(dst, src) \
    asm volatile("cp.async.cg.shared.global [%0], [%1], 16;" :: "r"(dst), "l"(src) : "memory")
#define CPCOMMIT() asm volatile("cp.async.commit_group;" ::: "memory")
template<int N> __device__ __forceinline__ void cpwait() {
    asm volatile("cp.async.wait_group %0;" :: "n"(N) : "memory");
}
__device__ __forceinline__ uint32_t s2u(const void* p) {
    uint32_t a;
    asm("{ .reg .u64 t; cvta.to.shared.u64 t, %1; cvt.u32.u64 %0, t; }" : "=r"(a) : "l"(p));
    return a;
}

// ---------------------------------------------------------------------------
// k_prep: W_F fp16 B-fragment image. grid=16, block=512.
// ---------------------------------------------------------------------------
__global__ void __launch_bounds__(512)
k_prep(const float* __restrict__ WF) {
    int tid = threadIdx.x;
    int t = blockIdx.x;
    int p = tid >> 5, l = tid & 31;
    int rq = l >> 2, cq = l & 3;
    int k0 = t * 16 + 2 * cq;
    int na = p * 16 + rq, nb = na + 8;
    uint4 qv;
    qv.x = packh2(WF[k0 * HH + na],       WF[(k0 + 1) * HH + na]);
    qv.y = packh2(WF[(k0 + 8) * HH + na], WF[(k0 + 9) * HH + na]);
    qv.z = packh2(WF[k0 * HH + nb],       WF[(k0 + 1) * HH + nb]);
    qv.w = packh2(WF[(k0 + 8) * HH + nb], WF[(k0 + 9) * HH + nb]);
    g_Bh[(t * 16 + p) * 32 + l] = qv;
}

// ---------------------------------------------------------------------------
// k_u: u[b][h] = dot(W_t[h], o_last[b]) for half the batches. One warp per
// (b,h), coalesced LDG + shfl reduce. grid=512, block=512; base selects half.
// ---------------------------------------------------------------------------
__global__ void __launch_bounds__(512)
k_u(const float* __restrict__ o, const float* __restrict__ Wt, int base) {
    int idx = base + blockIdx.x * 16 + (threadIdx.x >> 5);   // warp id
    int lane = threadIdx.x & 31;
    int b = idx >> 8, h = idx & 255;
    const float* wrow = Wt + h * HH;
    const float* olast = o + ((size_t)b * SS + (SS - 1)) * HH;
    float acc = 0.f;
#pragma unroll
    for (int j = 0; j < 8; j++) {
        int k = j * 32 + lane;
        acc = fmaf(__ldg(&wrow[k]), __ldg(&olast[k]), acc);
    }
#pragma unroll
    for (int off = 16; off; off >>= 1)
        acc += __shfl_xor_sync(0xFFFFFFFFu, acc, off);
    if (lane == 0) g_u[b * HH + h] = acc;
}

// ---------------------------------------------------------------------------
// k_main: M=64 tile, 256 threads, 2 CTAs/SM. 2-chunk bodies, one barrier per
// body, 4-slot A/B rings. grid=4096, block=256.  [round-12, unchanged]
// ---------------------------------------------------------------------------
__global__ void __launch_bounds__(256, 2)
k_main(const float* __restrict__ o, const float* __restrict__ vF) {
    extern __shared__ __align__(16) char smem[];
    const uint32_t sb = s2u(smem);
    const int tid = threadIdx.x, lane = tid & 31, wid = tid >> 5;
    const int tile = blockIdx.x;
    const int b = tile >> 6, s0 = (tile & 63) << 6;
    const int mw = wid & 1;   // M half (32 rows)
    const int nw = wid >> 1;  // N quarter (64 cols)
    const int rq = lane >> 2, cq = lane & 3;

    float* ush  = (float*)(smem + USH_OFF);
    float* vsh  = (float*)(smem + VSH_OFF);
    float* scT  = (float*)(smem + SCT_OFF);
    float* scF  = (float*)(smem + SCF_OFF);
    float* scFr = (float*)(smem + SCFR_OFF);
    float* red  = (float*)(smem + RED_OFF);

    const float* obase = o + ((size_t)(b * SS + s0)) * HH;

    auto issueB = [&](int c) {
        uint32_t bdst = sb + B_OFF + (c & 3) * 16384;
        const uint4* bsrc = g_Bh + c * 1024;
#pragma unroll
        for (int j = 0; j < 4; j++) {
            int idx = tid + j * 256;
            CP16(bdst + idx * 16, (const void*)(bsrc + idx));
        }
        CPCOMMIT();
    };

    const int arow = tid >> 2, q = tid & 3;
    const float4* aldg = (const float4*)obase + (size_t)arow * 64 + q * 2;
    const uint32_t axor = (uint32_t)(((arow >> 1) & 3) << 4);
    const uint32_t asts_off = AH_OFF + (uint32_t)arow * 64 + (((uint32_t)q * 16) ^ axor);

    float4 pf[2][2];          // pf slot = chunk & 1
    float sT = 0.f;
    auto ldgA = [&](int c) {
        pf[c & 1][0] = __ldg(aldg + c * 8);
        pf[c & 1][1] = __ldg(aldg + c * 8 + 1);
    };
    auto stsA = [&](int c) {
        const float4 u0 = *(const float4*)(ush + c * 32 + q * 8);
        const float4 u1 = *(const float4*)(ush + c * 32 + q * 8 + 4);
        float4 a0 = pf[c & 1][0], a1 = pf[c & 1][1];
        sT = fmaf(a0.x, u0.x, sT); sT = fmaf(a0.y, u0.y, sT);
        sT = fmaf(a0.z, u0.z, sT); sT = fmaf(a0.w, u0.w, sT);
        sT = fmaf(a1.x, u1.x, sT); sT = fmaf(a1.y, u1.y, sT);
        sT = fmaf(a1.z, u1.z, sT); sT = fmaf(a1.w, u1.w, sT);
        uint4 qq;
        qq.x = packh2(a0.x, a0.y); qq.y = packh2(a0.z, a0.w);
        qq.z = packh2(a1.x, a1.y); qq.w = packh2(a1.z, a1.w);
        *(uint4*)(smem + (c & 3) * 4096 + asts_off) = qq;
    };

    issueB(0); issueB(1);
    ush[tid] = __ldg(&g_u[b * HH + tid]);
    vsh[tid] = __ldg(&vF[tid]);
    ldgA(0); ldgA(1);
    __syncthreads();
    stsA(0); ldgA(2);
    stsA(1); ldgA(3);

    uint32_t arow_l = (uint32_t)(mw * 32 + (lane & 7) + ((lane >> 3) & 1) * 8);
    uint32_t slot16 = (uint32_t)((lane >> 4) << 4);
    uint32_t lrow[2], lxor[2];
#pragma unroll
    for (int mi = 0; mi < 2; mi++) {
        uint32_t r = arow_l + mi * 16;
        lrow[mi] = sb + AH_OFF + r * 64;
        lxor[mi] = ((r >> 1) & 3) << 4;
    }

    float acc[2][8][4];
#pragma unroll
    for (int mi = 0; mi < 2; mi++)
#pragma unroll
        for (int ni = 0; ni < 8; ni++)
#pragma unroll
            for (int j = 0; j < 4; j++) acc[mi][ni][j] = 0.f;

#pragma unroll
    for (int c = 0; c < 8; c += 2) {
        cpwait<0>();
        __syncthreads();
        if (c + 2 < 8) {
            issueB(c + 2); issueB(c + 3);
            stsA(c + 2);
            if (c + 4 < 8) ldgA(c + 4);
            stsA(c + 3);
            if (c + 5 < 8) ldgA(c + 5);
        }
#pragma unroll
        for (int s = 0; s < 2; s++) {
            const int cc = c + s;
            const uint4* Bsl = (const uint4*)(smem + B_OFF + (cc & 3) * 16384);
            const uint32_t aoff = (uint32_t)((cc & 3) * 4096);
#pragma unroll
            for (int t = 0; t < 2; t++) {
                uint32_t a[2][4];
#pragma unroll
                for (int mi = 0; mi < 2; mi++)
                    ldsm4(a[mi], lrow[mi] + aoff + (((uint32_t)(32 * t) + slot16) ^ lxor[mi]));
                const uint4* bp = Bsl + (t * 16 + nw * 4) * 32 + lane;
#pragma unroll
                for (int p = 0; p < 4; p++) {
                    uint4 bq = bp[p * 32];
#pragma unroll
                    for (int mi = 0; mi < 2; mi++) {
                        mma16(acc[mi][2 * p],     a[mi][0], a[mi][1], a[mi][2], a[mi][3], bq.x, bq.y);
                        mma16(acc[mi][2 * p + 1], a[mi][0], a[mi][1], a[mi][2], a[mi][3], bq.z, bq.w);
                    }
                }
            }
        }
    }

#pragma unroll
    for (int mi = 0; mi < 2; mi++) {
        float s0a = 0.f, s1a = 0.f;
#pragma unroll
        for (int ni = 0; ni < 8; ni++) {
            int n = nw * 64 + ni * 8 + cq * 2;
            float v0 = vsh[n], v1 = vsh[n + 1];
            s0a = fmaf(tanha(acc[mi][ni][0]), v0, s0a);
            s0a = fmaf(tanha(acc[mi][ni][1]), v1, s0a);
            s1a = fmaf(tanha(acc[mi][ni][2]), v0, s1a);
            s1a = fmaf(tanha(acc[mi][ni][3]), v1, s1a);
        }
        s0a += __shfl_xor_sync(0xFFFFFFFFu, s0a, 1);
        s0a += __shfl_xor_sync(0xFFFFFFFFu, s0a, 2);
        s1a += __shfl_xor_sync(0xFFFFFFFFu, s1a, 1);
        s1a += __shfl_xor_sync(0xFFFFFFFFu, s1a, 2);
        if (cq == 0) {
            int r = mw * 32 + mi * 16 + rq;
            scFr[nw * 64 + r] = s0a;
            scFr[nw * 64 + r + 8] = s1a;
        }
    }

    sT += __shfl_xor_sync(0xFFFFFFFFu, sT, 1);
    sT += __shfl_xor_sync(0xFFFFFFFFu, sT, 2);
    if ((lane & 3) == 0) scT[arow] = sT;
    __syncthreads();
    if (tid < 64)
        scF[tid] = scFr[tid] + scFr[64 + tid] + scFr[128 + tid] + scFr[192 + tid];
    __syncthreads();

    float vv = 0.f, ee = 0.f;
    float* arr = (tid < 64) ? scT : scF;
    int i = tid & 63;
    if (tid < 128) {
        vv = arr[i];
        float m = vv;
#pragma unroll
        for (int off = 16; off; off >>= 1)
            m = fmaxf(m, __shfl_xor_sync(0xFFFFFFFFu, m, off));
        if (lane == 0) red[wid] = m;
    }
    __syncthreads();
    float M = 0.f;
    if (tid < 128) {
        M = (tid < 64) ? fmaxf(red[0], red[1]) : fmaxf(red[2], red[3]);
        ee = __expf(vv - M);
        float s = ee;
#pragma unroll
        for (int off = 16; off; off >>= 1)
            s += __shfl_xor_sync(0xFFFFFFFFu, s, off);
        if (lane == 0) red[16 + wid] = s;
    }
    __syncthreads();
    if (tid < 128) arr[i] = ee;
    __syncthreads();
    if (tid == 0)  { g_mT[tile] = M; g_sT[tile] = red[16] + red[17]; }
    if (tid == 64) { g_mF[tile] = M; g_sF[tile] = red[18] + red[19]; }

    {
        int g = tid >> 6, hc = tid & 63;
        const float4* orow = (const float4*)obase + (size_t)(g * 16) * 64 + hc;
        float4 aT = {0.f, 0.f, 0.f, 0.f}, aF = {0.f, 0.f, 0.f, 0.f};
#pragma unroll 8
        for (int r = 0; r < 16; r++) {
            float4 ov = __ldg(orow + (size_t)r * 64);
            float wT = scT[g * 16 + r], wF = scF[g * 16 + r];
            aT.x = fmaf(wT, ov.x, aT.x); aT.y = fmaf(wT, ov.y, aT.y);
            aT.z = fmaf(wT, ov.z, aT.z); aT.w = fmaf(wT, ov.w, aT.w);
            aF.x = fmaf(wF, ov.x, aF.x); aF.y = fmaf(wF, ov.y, aF.y);
            aF.z = fmaf(wF, ov.z, aF.z); aF.w = fmaf(wF, ov.w, aF.w);
        }
        float* pTs = (float*)(smem + PTS_OFF);
        float* pFs = (float*)(smem + PFS_OFF);
        ((float4*)(pTs + g * 256))[hc] = aT;
        ((float4*)(pFs + g * 256))[hc] = aF;
    }
    __syncthreads();
    {
        float* pTs = (float*)(smem + PTS_OFF);
        float* pFs = (float*)(smem + PFS_OFF);
        float a = pTs[tid] + pTs[256 + tid] + pTs[512 + tid] + pTs[768 + tid];
        float f = pFs[tid] + pFs[256 + tid] + pFs[512 + tid] + pFs[768 + tid];
        g_pT[tile * HH + tid] = a;
        g_pF[tile * HH + tid] = f;
    }
}

// ---------------------------------------------------------------------------
// k_combine: exact split-softmax merge over 64 s-tiles per batch.
// grid = (BB, 2), block = 1024.  [round-11, unchanged]
// ---------------------------------------------------------------------------
__global__ void __launch_bounds__(1024)
k_combine(float* __restrict__ out) {
    __shared__ float sm_w[64];
    __shared__ float sm_s[64];
    __shared__ float po[4][HH];
    int b = blockIdx.x, which = blockIdx.y;
    int tid = threadIdx.x;
    int g = tid >> 8, h = tid & 255;
    const float* gm = which ? g_mF : g_mT;
    const float* gs = which ? g_sF : g_sT;
    const float* gp = which ? g_pF : g_pT;

    if (tid < 64) {
        sm_w[tid] = __ldg(&gm[b * 64 + tid]);
        sm_s[tid] = __ldg(&gs[b * 64 + tid]);
    }
    __syncthreads();
    float M = -1e30f;
#pragma unroll
    for (int c = 0; c < 64; c++) M = fmaxf(M, sm_w[c]);
    __syncthreads();
    if (tid < 64) sm_w[tid] = __expf(sm_w[tid] - M);
    __syncthreads();

    float oV = 0.f;
#pragma unroll
    for (int cc = 0; cc < 16; cc++) {
        int c = g * 16 + cc;
        oV = fmaf(sm_w[c], __ldg(&gp[(b * 64 + c) * HH + h]), oV);
    }
    po[g][h] = oV;
    __syncthreads();
    if (tid < HH) {
        float S = 0.f;
#pragma unroll
        for (int c = 0; c < 64; c++) S = fmaf(sm_w[c], sm_s[c], S);
        float v = po[0][tid] + po[1][tid] + po[2][tid] + po[3][tid];
        out[b * 2 * HH + which * HH + tid] = v / S;
    }
}

// ---------------------------------------------------------------------------
extern "C" void kernel_launch(void* const* d_in, const int* in_sizes, int n_in,
                              void* d_out, int out_size) {
    const float* o  = (const float*)d_in[0];
    const float* Wt = (const float*)d_in[1];
    const float* WF = (const float*)d_in[2];
    const float* vF = (const float*)d_in[3];
    float* out = (float*)d_out;

    cudaFuncSetAttribute(k_main, cudaFuncAttributeMaxDynamicSharedMemorySize, SMEM_TOTAL);

    k_prep<<<16, 512>>>(WF);            // launch 0
    k_u<<<512, 512>>>(o, Wt, 0);        // launch 1 (batches 0..31)
    k_u<<<512, 512>>>(o, Wt, 8192);     // launch 2 (batches 32..63)
    k_main<<<NTILES, 256, SMEM_TOTAL>>>(o, vF);   // launch 3  <- profiled
    k_combine<<<dim3(BB, 2), 1024>>>(out);        // launch 4
}

// round 14
// speedup vs baseline: 1.0688x; 1.0688x over previous
#include <cuda_runtime.h>
#include <cuda_fp16.h>
#include <math.h>
#include <stdint.h>

#define BB 64
#define SS 4096
#define HH 256
#define NTILES 4096            // BB*SS/64  (M=64 tiles)

// ---------------- device-global scratch (no allocation allowed) -------------
__device__ float g_u[BB * HH];            // W_t @ o_last per batch (fp32)
__device__ uint4 g_Bh[16 * 16 * 32];      // W_F fp16 m16n8k16 B-fragment image (128 KB)
__device__ float g_pT[NTILES * HH];
__device__ float g_pF[NTILES * HH];
__device__ float g_mT[NTILES], g_sT[NTILES], g_mF[NTILES], g_sF[NTILES];

// ---------------- SMEM map (bytes), 28288 total -> 2 CTAs/SM (reg-capped) ---
#define AH_OFF    0            // 4 slots x 4096 (64 rows x 64B fp16) = 16384
#define USH_OFF   16384        // 256 floats
#define VSH_OFF   17408        // 256 floats
#define SCT_OFF   18432        // 64 floats
#define SCF_OFF   18688        // 64 floats
#define SCFR_OFF  18944        // 4 x 64 floats = 1024
#define RED_OFF   19968        // 32 floats
#define PTS_OFF   20096        // 4 x 256 floats = 4096
#define PFS_OFF   24192        // 4 x 256 floats = 4096
#define SMEM_TOTAL 28288

// ---------------- helpers ----------------------------------------------------
__device__ __forceinline__ uint32_t packh2(float lo, float hi) {
    __half2 h = __floats2half2_rn(lo, hi);
    return *(uint32_t*)&h;
}
__device__ __forceinline__ float tanha(float x) {
    float y;
    asm("tanh.approx.f32 %0, %1;" : "=f"(y) : "f"(x));
    return y;
}
__device__ __forceinline__ void mma16(float* c, uint32_t a0, uint32_t a1,
                                      uint32_t a2, uint32_t a3,
                                      uint32_t b0, uint32_t b1) {
    asm volatile(
        "mma.sync.aligned.m16n8k16.row.col.f32.f16.f16.f32 "
        "{%0,%1,%2,%3}, {%4,%5,%6,%7}, {%8,%9}, {%0,%1,%2,%3};"
        : "+f"(c[0]), "+f"(c[1]), "+f"(c[2]), "+f"(c[3])
        : "r"(a0), "r"(a1), "r"(a2), "r"(a3), "r"(b0), "r"(b1));
}
__device__ __forceinline__ void ldsm4(uint32_t* a, uint32_t addr) {
    asm volatile("ldmatrix.sync.aligned.m8n8.x4.shared.b16 {%0,%1,%2,%3}, [%4];"
                 : "=r"(a[0]), "=r"(a[1]), "=r"(a[2]), "=r"(a[3]) : "r"(addr));
}
// B fragment load: non-coherent, keep resident in L1 (evict_last)
__device__ __forceinline__ uint4 ldgB(const uint4* p) {
    uint4 v;
    asm volatile("ld.global.nc.L1::evict_last.v4.u32 {%0,%1,%2,%3}, [%4];"
                 : "=r"(v.x), "=r"(v.y), "=r"(v.z), "=r"(v.w) : "l"(p));
    return v;
}
__device__ __forceinline__ uint32_t s2u(const void* p) {
    uint32_t a;
    asm("{ .reg .u64 t; cvta.to.shared.u64 t, %1; cvt.u32.u64 %0, t; }" : "=r"(a) : "l"(p));
    return a;
}

// ---------------------------------------------------------------------------
// k_init: blocks 0..15 build the W_F fp16 B-fragment image;
//         blocks 16..1039 compute u[b][h] via coalesced warp-dot.
// ---------------------------------------------------------------------------
__global__ void __launch_bounds__(512)
k_init(const float* __restrict__ o, const float* __restrict__ Wt,
       const float* __restrict__ WF) {
    int tid = threadIdx.x;
    if (blockIdx.x < 16) {
        int t = blockIdx.x;
        int p = tid >> 5, l = tid & 31;
        int rq = l >> 2, cq = l & 3;
        int k0 = t * 16 + 2 * cq;
        int na = p * 16 + rq, nb = na + 8;
        uint4 q;
        q.x = packh2(WF[k0 * HH + na],       WF[(k0 + 1) * HH + na]);
        q.y = packh2(WF[(k0 + 8) * HH + na], WF[(k0 + 9) * HH + na]);
        q.z = packh2(WF[k0 * HH + nb],       WF[(k0 + 1) * HH + nb]);
        q.w = packh2(WF[(k0 + 8) * HH + nb], WF[(k0 + 9) * HH + nb]);
        g_Bh[(t * 16 + p) * 32 + l] = q;
    } else {
        int idx = (blockIdx.x - 16) * 16 + (tid >> 5);
        int lane = tid & 31;
        int b = idx >> 8, h = idx & 255;
        const float* wrow = Wt + h * HH;
        const float* olast = o + ((size_t)b * SS + (SS - 1)) * HH;
        float acc = 0.f;
#pragma unroll
        for (int j = 0; j < 8; j++) {
            int k = j * 32 + lane;
            acc = fmaf(__ldg(&wrow[k]), __ldg(&olast[k]), acc);
        }
#pragma unroll
        for (int off = 16; off; off >>= 1)
            acc += __shfl_xor_sync(0xFFFFFFFFu, acc, off);
        if (lane == 0) g_u[b * HH + h] = acc;
    }
}

// ---------------------------------------------------------------------------
// k_main: M=64 tile, 256 threads, 2 CTAs/SM. B fragments read DIRECTLY from
// global (L1-resident, evict_last) — no B SMEM, no cp.async. A keeps the
// LDG->fp32-regs (folded exact time scores) -> fp16 STS -> ldmatrix path with
// a 4-slot ring, one barrier per 2 K-chunks. grid=4096, block=256.
// ---------------------------------------------------------------------------
__global__ void __launch_bounds__(256, 2)
k_main(const float* __restrict__ o, const float* __restrict__ vF) {
    extern __shared__ __align__(16) char smem[];
    const uint32_t sb = s2u(smem);
    const int tid = threadIdx.x, lane = tid & 31, wid = tid >> 5;
    const int tile = blockIdx.x;
    const int b = tile >> 6, s0 = (tile & 63) << 6;
    const int mw = wid & 1;   // M half (32 rows)
    const int nw = wid >> 1;  // N quarter (64 cols)
    const int rq = lane >> 2, cq = lane & 3;

    float* ush  = (float*)(smem + USH_OFF);
    float* vsh  = (float*)(smem + VSH_OFF);
    float* scT  = (float*)(smem + SCT_OFF);
    float* scF  = (float*)(smem + SCF_OFF);
    float* scFr = (float*)(smem + SCFR_OFF);
    float* red  = (float*)(smem + RED_OFF);

    const float* obase = o + ((size_t)(b * SS + s0)) * HH;

    // ---- per-warp B fragment base pointer (global, fragment-ordered) ----
    const uint4* bwp = g_Bh + (nw * 4) * 32 + lane;

    // ---- A prefetch (LDG->fp32 regs), fold time-score FMAs, fp16 STS ----
    const int arow = tid >> 2, q = tid & 3;
    const float4* aldg = (const float4*)obase + (size_t)arow * 64 + q * 2;
    const uint32_t axor = (uint32_t)(((arow >> 1) & 3) << 4);
    const uint32_t asts_off = AH_OFF + (uint32_t)arow * 64 + (((uint32_t)q * 16) ^ axor);

    float4 pf[2][2];          // pf slot = chunk & 1
    float sT = 0.f;
    auto ldgA = [&](int c) {
        pf[c & 1][0] = __ldg(aldg + c * 8);
        pf[c & 1][1] = __ldg(aldg + c * 8 + 1);
    };
    auto stsA = [&](int c) {  // writes A slot (c & 3), consumes pf[c & 1]
        const float4 u0 = *(const float4*)(ush + c * 32 + q * 8);
        const float4 u1 = *(const float4*)(ush + c * 32 + q * 8 + 4);
        float4 a0 = pf[c & 1][0], a1 = pf[c & 1][1];
        sT = fmaf(a0.x, u0.x, sT); sT = fmaf(a0.y, u0.y, sT);
        sT = fmaf(a0.z, u0.z, sT); sT = fmaf(a0.w, u0.w, sT);
        sT = fmaf(a1.x, u1.x, sT); sT = fmaf(a1.y, u1.y, sT);
        sT = fmaf(a1.z, u1.z, sT); sT = fmaf(a1.w, u1.w, sT);
        uint4 qq;
        qq.x = packh2(a0.x, a0.y); qq.y = packh2(a0.z, a0.w);
        qq.z = packh2(a1.x, a1.y); qq.w = packh2(a1.z, a1.w);
        *(uint4*)(smem + (c & 3) * 4096 + asts_off) = qq;
    };

    // ---- prologue ----
    ush[tid] = __ldg(&g_u[b * HH + tid]);
    vsh[tid] = __ldg(&vF[tid]);
    ldgA(0); ldgA(1);
    __syncthreads();          // ush visible before stsA(0)
    stsA(0); ldgA(2);
    stsA(1); ldgA(3);

    // ---- ldmatrix lane addressing (per mi) ----
    uint32_t arow_l = (uint32_t)(mw * 32 + (lane & 7) + ((lane >> 3) & 1) * 8);
    uint32_t slot16 = (uint32_t)((lane >> 4) << 4);
    uint32_t lrow[2], lxor[2];
#pragma unroll
    for (int mi = 0; mi < 2; mi++) {
        uint32_t r = arow_l + mi * 16;
        lrow[mi] = sb + AH_OFF + r * 64;
        lxor[mi] = ((r >> 1) & 3) << 4;
    }

    float acc[2][8][4];
#pragma unroll
    for (int mi = 0; mi < 2; mi++)
#pragma unroll
        for (int ni = 0; ni < 8; ni++)
#pragma unroll
            for (int j = 0; j < 4; j++) acc[mi][ni][j] = 0.f;

    // ---- mainloop: 4 bodies of 2 K-chunks; one barrier per body ----
#pragma unroll
    for (int c = 0; c < 8; c += 2) {
        __syncthreads();       // A slots (c,c+1) visible; body c-2 reads done
        if (c + 2 < 8) {
            stsA(c + 2);
            if (c + 4 < 8) ldgA(c + 4);
            stsA(c + 3);
            if (c + 5 < 8) ldgA(c + 5);
        }
#pragma unroll
        for (int s = 0; s < 2; s++) {
            const int cc = c + s;
            const uint32_t aoff = (uint32_t)((cc & 3) * 4096);
            const uint4* bch = bwp + cc * 1024;
#pragma unroll
            for (int t = 0; t < 2; t++) {
                uint32_t a[2][4];
#pragma unroll
                for (int mi = 0; mi < 2; mi++)
                    ldsm4(a[mi], lrow[mi] + aoff + (((uint32_t)(32 * t) + slot16) ^ lxor[mi]));
                const uint4* bp = bch + t * 512;
#pragma unroll
                for (int p = 0; p < 4; p++) {
                    uint4 bq = ldgB(bp + p * 32);
#pragma unroll
                    for (int mi = 0; mi < 2; mi++) {
                        mma16(acc[mi][2 * p],     a[mi][0], a[mi][1], a[mi][2], a[mi][3], bq.x, bq.y);
                        mma16(acc[mi][2 * p + 1], a[mi][0], a[mi][1], a[mi][2], a[mi][3], bq.z, bq.w);
                    }
                }
            }
        }
    }

    // ---- feature scores: sf[r] = sum_n tanh(z[r,n]) * v[n] ----
#pragma unroll
    for (int mi = 0; mi < 2; mi++) {
        float s0a = 0.f, s1a = 0.f;
#pragma unroll
        for (int ni = 0; ni < 8; ni++) {
            int n = nw * 64 + ni * 8 + cq * 2;
            float v0 = vsh[n], v1 = vsh[n + 1];
            s0a = fmaf(tanha(acc[mi][ni][0]), v0, s0a);
            s0a = fmaf(tanha(acc[mi][ni][1]), v1, s0a);
            s1a = fmaf(tanha(acc[mi][ni][2]), v0, s1a);
            s1a = fmaf(tanha(acc[mi][ni][3]), v1, s1a);
        }
        s0a += __shfl_xor_sync(0xFFFFFFFFu, s0a, 1);
        s0a += __shfl_xor_sync(0xFFFFFFFFu, s0a, 2);
        s1a += __shfl_xor_sync(0xFFFFFFFFu, s1a, 1);
        s1a += __shfl_xor_sync(0xFFFFFFFFu, s1a, 2);
        if (cq == 0) {
            int r = mw * 32 + mi * 16 + rq;
            scFr[nw * 64 + r] = s0a;
            scFr[nw * 64 + r + 8] = s1a;
        }
    }

    // ---- exact fp32 time scores: reduce 4 threads sharing a row ----
    sT += __shfl_xor_sync(0xFFFFFFFFu, sT, 1);
    sT += __shfl_xor_sync(0xFFFFFFFFu, sT, 2);
    if ((lane & 3) == 0) scT[arow] = sT;
    __syncthreads();
    if (tid < 64)
        scF[tid] = scFr[tid] + scFr[64 + tid] + scFr[128 + tid] + scFr[192 + tid];
    __syncthreads();

    // ---- split-softmax partials (threads 0..127: warps 0-1 T, 2-3 F) ----
    float vv = 0.f, ee = 0.f;
    float* arr = (tid < 64) ? scT : scF;
    int i = tid & 63;
    if (tid < 128) {
        vv = arr[i];
        float m = vv;
#pragma unroll
        for (int off = 16; off; off >>= 1)
            m = fmaxf(m, __shfl_xor_sync(0xFFFFFFFFu, m, off));
        if (lane == 0) red[wid] = m;
    }
    __syncthreads();
    float M = 0.f;
    if (tid < 128) {
        M = (tid < 64) ? fmaxf(red[0], red[1]) : fmaxf(red[2], red[3]);
        ee = __expf(vv - M);
        float s = ee;
#pragma unroll
        for (int off = 16; off; off >>= 1)
            s += __shfl_xor_sync(0xFFFFFFFFu, s, off);
        if (lane == 0) red[16 + wid] = s;
    }
    __syncthreads();
    if (tid < 128) arr[i] = ee;
    __syncthreads();
    if (tid == 0)  { g_mT[tile] = M; g_sT[tile] = red[16] + red[17]; }
    if (tid == 64) { g_mF[tile] = M; g_sF[tile] = red[18] + red[19]; }

    // ---- exact fp32 weighted sums: re-read o (L2-hot) via LDG.128 ----
    {
        int g = tid >> 6, hc = tid & 63;
        const float4* orow = (const float4*)obase + (size_t)(g * 16) * 64 + hc;
        float4 aT = {0.f, 0.f, 0.f, 0.f}, aF = {0.f, 0.f, 0.f, 0.f};
#pragma unroll 8
        for (int r = 0; r < 16; r++) {
            float4 ov = __ldg(orow + (size_t)r * 64);
            float wT = scT[g * 16 + r], wF = scF[g * 16 + r];
            aT.x = fmaf(wT, ov.x, aT.x); aT.y = fmaf(wT, ov.y, aT.y);
            aT.z = fmaf(wT, ov.z, aT.z); aT.w = fmaf(wT, ov.w, aT.w);
            aF.x = fmaf(wF, ov.x, aF.x); aF.y = fmaf(wF, ov.y, aF.y);
            aF.z = fmaf(wF, ov.z, aF.z); aF.w = fmaf(wF, ov.w, aF.w);
        }
        float* pTs = (float*)(smem + PTS_OFF);
        float* pFs = (float*)(smem + PFS_OFF);
        ((float4*)(pTs + g * 256))[hc] = aT;
        ((float4*)(pFs + g * 256))[hc] = aF;
    }
    __syncthreads();
    {
        float* pTs = (float*)(smem + PTS_OFF);
        float* pFs = (float*)(smem + PFS_OFF);
        float a = pTs[tid] + pTs[256 + tid] + pTs[512 + tid] + pTs[768 + tid];
        float f = pFs[tid] + pFs[256 + tid] + pFs[512 + tid] + pFs[768 + tid];
        g_pT[tile * HH + tid] = a;
        g_pF[tile * HH + tid] = f;
    }
}

// ---------------------------------------------------------------------------
// k_combine: exact split-softmax merge over 64 s-tiles per batch.
// grid = (BB, 2), block = 1024.
// ---------------------------------------------------------------------------
__global__ void __launch_bounds__(1024)
k_combine(float* __restrict__ out) {
    __shared__ float sm_w[64];
    __shared__ float sm_s[64];
    __shared__ float po[4][HH];
    int b = blockIdx.x, which = blockIdx.y;
    int tid = threadIdx.x;
    int g = tid >> 8, h = tid & 255;
    const float* gm = which ? g_mF : g_mT;
    const float* gs = which ? g_sF : g_sT;
    const float* gp = which ? g_pF : g_pT;

    if (tid < 64) {
        sm_w[tid] = __ldg(&gm[b * 64 + tid]);
        sm_s[tid] = __ldg(&gs[b * 64 + tid]);
    }
    __syncthreads();
    float M = -1e30f;
#pragma unroll
    for (int c = 0; c < 64; c++) M = fmaxf(M, sm_w[c]);
    __syncthreads();
    if (tid < 64) sm_w[tid] = __expf(sm_w[tid] - M);
    __syncthreads();

    float oV = 0.f;
#pragma unroll
    for (int cc = 0; cc < 16; cc++) {
        int c = g * 16 + cc;
        oV = fmaf(sm_w[c], __ldg(&gp[(b * 64 + c) * HH + h]), oV);
    }
    po[g][h] = oV;
    __syncthreads();
    if (tid < HH) {
        float S = 0.f;
#pragma unroll
        for (int c = 0; c < 64; c++) S = fmaf(sm_w[c], sm_s[c], S);
        float v = po[0][tid] + po[1][tid] + po[2][tid] + po[3][tid];
        out[b * 2 * HH + which * HH + tid] = v / S;
    }
}

// ---------------------------------------------------------------------------
extern "C" void kernel_launch(void* const* d_in, const int* in_sizes, int n_in,
                              void* d_out, int out_size) {
    const float* o  = (const float*)d_in[0];
    const float* Wt = (const float*)d_in[1];
    const float* WF = (const float*)d_in[2];
    const float* vF = (const float*)d_in[3];
    float* out = (float*)d_out;

    cudaFuncSetAttribute(k_main, cudaFuncAttributeMaxDynamicSharedMemorySize, SMEM_TOTAL);

    k_init<<<1040, 512>>>(o, Wt, WF);
    k_main<<<NTILES, 256, SMEM_TOTAL>>>(o, vF);
    k_combine<<<dim3(BB, 2), 1024>>>(out);
}